// round 15
// baseline (speedup 1.0000x reference)
#include <cuda_runtime.h>
#include <cuda_fp16.h>
#include <math.h>
#include <stdint.h>

#define BB   2
#define SS   2048
#define HIDN 2048
#define NH   16
#define NKV  4
#define DD   128
#define MAXS 4096
#define GEMM_K 2048
#define QSCALE 0.08838834764831845f
#define L2E 1.4426950408889634f

// ---------------- scratch ----------------
__device__ __half g_h16 [(size_t)BB*SS*GEMM_K];
__device__ __half g_q16 [(size_t)BB*SS*NH*DD];
__device__ __half g_k16 [(size_t)BB*SS*NKV*DD];
__device__ __half g_v16 [(size_t)BB*SS*NKV*DD];
__device__ __half g_ctx16[(size_t)BB*SS*NH*DD];
__device__ __half g_w16 [(size_t)3072*GEMM_K];
__device__ __half g_wo16[(size_t)2048*GEMM_K];

// ---------------- helpers ----------------
__device__ __forceinline__ uint32_t smem_u32(const void* p) {
    uint32_t a;
    asm("{ .reg .u64 t; cvta.to.shared.u64 t, %1; cvt.u32.u64 %0, t; }" : "=r"(a) : "l"(p));
    return a;
}
__device__ __forceinline__ void cp16(uint32_t dst, const void* src) {
    asm volatile("cp.async.cg.shared.global [%0], [%1], 16;" :: "r"(dst), "l"(src));
}
#define CP_COMMIT() asm volatile("cp.async.commit_group;" ::: "memory")
#define CP_WAIT(n)  asm volatile("cp.async.wait_group %0;" :: "n"(n) : "memory")

__device__ __forceinline__ void ldsm4(uint32_t* r, uint32_t addr) {
    asm volatile("ldmatrix.sync.aligned.m8n8.x4.shared.b16 {%0,%1,%2,%3}, [%4];"
        : "=r"(r[0]), "=r"(r[1]), "=r"(r[2]), "=r"(r[3]) : "r"(addr));
}
__device__ __forceinline__ void ldsm4t(uint32_t* r, uint32_t addr) {
    asm volatile("ldmatrix.sync.aligned.m8n8.x4.trans.shared.b16 {%0,%1,%2,%3}, [%4];"
        : "=r"(r[0]), "=r"(r[1]), "=r"(r[2]), "=r"(r[3]) : "r"(addr));
}
__device__ __forceinline__ void mma16816(float* d, const uint32_t* a, const uint32_t* b) {
    asm volatile(
        "mma.sync.aligned.m16n8k16.row.col.f32.f16.f16.f32 "
        "{%0,%1,%2,%3}, {%4,%5,%6,%7}, {%8,%9}, {%0,%1,%2,%3};"
        : "+f"(d[0]), "+f"(d[1]), "+f"(d[2]), "+f"(d[3])
        : "r"(a[0]), "r"(a[1]), "r"(a[2]), "r"(a[3]), "r"(b[0]), "r"(b[1]));
}
__device__ __forceinline__ uint32_t expx2_h2(float t0, float t1) {
    uint32_t h;
    asm("cvt.rn.f16x2.f32 %0, %1, %2;" : "=r"(h) : "f"(t1), "f"(t0));
    asm("ex2.approx.f16x2 %0, %0;" : "+r"(h));
    return h;
}

// ---------------- RMSNorm -> fp16 ----------------
__global__ void rmsnorm16_kernel(const float* __restrict__ x,
                                 const float* __restrict__ w,
                                 __half* __restrict__ h)
{
    int row = blockIdx.x;
    const float* xr = x + (size_t)row * HIDN;
    float ss = 0.f;
    for (int i = threadIdx.x; i < HIDN; i += blockDim.x) { float v = xr[i]; ss += v * v; }
    __shared__ float sred[32];
    #pragma unroll
    for (int o = 16; o > 0; o >>= 1) ss += __shfl_xor_sync(0xffffffffu, ss, o);
    if ((threadIdx.x & 31) == 0) sred[threadIdx.x >> 5] = ss;
    __syncthreads();
    if (threadIdx.x < 32) {
        float v = (threadIdx.x < (blockDim.x >> 5)) ? sred[threadIdx.x] : 0.f;
        #pragma unroll
        for (int o = 16; o > 0; o >>= 1) v += __shfl_xor_sync(0xffffffffu, v, o);
        if (threadIdx.x == 0) sred[0] = v;
    }
    __syncthreads();
    float rstd = rsqrtf(sred[0] / (float)HIDN + 1e-6f);
    for (int i = threadIdx.x; i < HIDN; i += blockDim.x)
        h[(size_t)row * HIDN + i] = __float2half_rn(xr[i] * rstd * w[i]);
}

// ---------------- weight transposes ----------------
__global__ void transpose_qkv_kernel(const float* __restrict__ Wq,
                                     const float* __restrict__ Wk,
                                     const float* __restrict__ Wv,
                                     __half* __restrict__ o)
{
    __shared__ float t[32][33];
    int k0 = blockIdx.x * 32, ng0 = blockIdx.y * 32;
    const float* W; int Nsrc; int nsrc0;
    if (ng0 < 2048)      { W = Wq; Nsrc = 2048; nsrc0 = ng0; }
    else if (ng0 < 2560) { W = Wk; Nsrc = 512;  nsrc0 = ng0 - 2048; }
    else                 { W = Wv; Nsrc = 512;  nsrc0 = ng0 - 2560; }
    int tx = threadIdx.x & 31, ty = threadIdx.x >> 5;
    #pragma unroll
    for (int i = 0; i < 4; i++)
        t[ty + i * 8][tx] = W[(size_t)(k0 + ty + i * 8) * Nsrc + nsrc0 + tx];
    __syncthreads();
    #pragma unroll
    for (int i = 0; i < 4; i++)
        o[(size_t)(ng0 + ty + i * 8) * GEMM_K + k0 + tx] = __float2half_rn(t[tx][ty + i * 8]);
}

__global__ void transpose_wo_kernel(const float* __restrict__ W, __half* __restrict__ o)
{
    __shared__ float t[32][33];
    int k0 = blockIdx.x * 32, n0 = blockIdx.y * 32;
    int tx = threadIdx.x & 31, ty = threadIdx.x >> 5;
    #pragma unroll
    for (int i = 0; i < 4; i++)
        t[ty + i * 8][tx] = W[(size_t)(k0 + ty + i * 8) * 2048 + n0 + tx];
    __syncthreads();
    #pragma unroll
    for (int i = 0; i < 4; i++)
        o[(size_t)(n0 + ty + i * 8) * GEMM_K + k0 + tx] = __float2half_rn(t[tx][ty + i * 8]);
}

// ---------------- fp16 HMMA GEMM: CTA 128x256, warp 64x64, BK=32, 4 stages ----------------
// KSB = 80 bytes: multiple of 16 (cp.async + ldmatrix alignment), and the 8-row
// ldmatrix phase addresses mod 128B are {0,80,32,112,64,16,96,48} -> conflict-free.
#define KSB   80
#define ATL   (128*KSB)                // 10240
#define BTL   (256*KSB)                // 20480
#define STG   (ATL+BTL)                // 30720
#define NSTG  4
#define GSMEM (NSTG*STG)               // 122880

template<int MODE>   // 0 = QKV (bias + rope + cache), 1 = Wo (residual, fp32 out)
__global__ void __launch_bounds__(256) h16_gemm_kernel(
    const __half* __restrict__ A, const __half* __restrict__ Bm,
    const float* __restrict__ bq, const float* __restrict__ bk, const float* __restrict__ bv,
    const float* __restrict__ resid,
    const float* __restrict__ cosb, const float* __restrict__ sinb,
    const int* __restrict__ pos,
    float* __restrict__ kcache, float* __restrict__ vcache,
    float* __restrict__ outf)
{
    extern __shared__ char smem[];
    uint32_t sb = smem_u32(smem);
    const int tid = threadIdx.x, lane = tid & 31, wid = tid >> 5;
    const int wm = wid >> 2, wn = wid & 3;          // 2 x 4 warps, 64x64 tiles
    const int g = lane >> 2, c = lane & 3;
    const int lq = lane & 15, lh = lane >> 4;
    const int rowblk = blockIdx.y * 128, colblk = blockIdx.x * 256;

    // cp.async plan: 6 chunks/thread (2 A + 4 B)
    const __half* gsrc[6];
    uint32_t soff[6];
    #pragma unroll
    for (int rep = 0; rep < 2; rep++) {
        int lin = rep * 256 + tid;
        int row = lin >> 2, sec = lin & 3;
        gsrc[rep] = A + (size_t)(rowblk + row) * GEMM_K + sec * 8;
        soff[rep] = (uint32_t)(row * KSB + sec * 16);
    }
    #pragma unroll
    for (int rep = 0; rep < 4; rep++) {
        int lin = rep * 256 + tid;
        int row = lin >> 2, sec = lin & 3;
        gsrc[2 + rep] = Bm + (size_t)(colblk + row) * GEMM_K + sec * 8;
        soff[2 + rep] = (uint32_t)(ATL + row * KSB + sec * 16);
    }

    float acc[4][8][4];
    #pragma unroll
    for (int mt = 0; mt < 4; mt++)
        #pragma unroll
        for (int nt = 0; nt < 8; nt++)
            #pragma unroll
            for (int r = 0; r < 4; r++) acc[mt][nt][r] = 0.f;

    // prologue: stages 0..2
    #pragma unroll
    for (int st = 0; st < NSTG - 1; st++) {
        uint32_t stb = sb + (uint32_t)(st * STG);
        #pragma unroll
        for (int rep = 0; rep < 6; rep++) cp16(stb + soff[rep], gsrc[rep] + st * 32);
        CP_COMMIT();
    }

    const int NCH = GEMM_K / 32;   // 64
    for (int kc = 0; kc < NCH; kc++) {
        CP_WAIT(2);
        __syncthreads();
        // issue stage kc+3 into buffer (kc+3)%4 == (kc-1)%4 (freed by loop-end barrier)
        if (kc + NSTG - 1 < NCH) {
            uint32_t stb = sb + (uint32_t)(((kc + NSTG - 1) & (NSTG - 1)) * STG);
            #pragma unroll
            for (int rep = 0; rep < 6; rep++)
                cp16(stb + soff[rep], gsrc[rep] + (kc + NSTG - 1) * 32);
        }
        CP_COMMIT();

        uint32_t base = sb + (uint32_t)((kc & (NSTG - 1)) * STG);
        #pragma unroll
        for (int kk = 0; kk < 2; kk++) {
            uint32_t af[4][4], bf[8][2];
            #pragma unroll
            for (int mt = 0; mt < 4; mt++)
                ldsm4(af[mt], base + (uint32_t)((wm * 64 + mt * 16 + lq) * KSB
                                                + (kk * 16 + 8 * lh) * 2));
            #pragma unroll
            for (int ntp = 0; ntp < 4; ntp++) {
                uint32_t r[4];
                ldsm4(r, base + (uint32_t)(ATL + (wn * 64 + ntp * 16 + lq) * KSB
                                           + (kk * 16 + 8 * lh) * 2));
                bf[2 * ntp][0] = r[0]; bf[2 * ntp][1] = r[2];
                bf[2 * ntp + 1][0] = r[1]; bf[2 * ntp + 1][1] = r[3];
            }
            #pragma unroll
            for (int mt = 0; mt < 4; mt++)
                #pragma unroll
                for (int nt = 0; nt < 8; nt++) mma16816(acc[mt][nt], af[mt], bf[nt]);
        }
        __syncthreads();
    }

    if (MODE == 0) {
        int cls = (colblk < 2048) ? 0 : (colblk < 2560 ? 1 : 2);
        #pragma unroll
        for (int mt = 0; mt < 4; mt++)
            #pragma unroll
            for (int nt = 0; nt < 8; nt++) {
                int cl = wn * 64 + nt * 8 + 2 * c;
                int gcol = colblk + cl;
                #pragma unroll
                for (int hf = 0; hf < 2; hf++) {
                    int r = rowblk + wm * 64 + mt * 16 + g + hf * 8;
                    float v0 = acc[mt][nt][hf * 2 + 0];
                    float v1 = acc[mt][nt][hf * 2 + 1];
                    if (cls == 0) {
                        int hh = gcol >> 7, d = gcol & 127;
                        v0 += bq[gcol]; v1 += bq[gcol + 1];
                        float c0 = cosb[(size_t)r * DD + d],     s0 = sinb[(size_t)r * DD + d];
                        float c1 = cosb[(size_t)r * DD + d + 1], s1 = sinb[(size_t)r * DD + d + 1];
                        float y0 = (v0 * c0 - v1 * s0) * QSCALE;
                        float y1 = (v1 * c1 + v0 * s1) * QSCALE;
                        *(__half2*)(g_q16 + ((size_t)r * NH + hh) * DD + d) = __floats2half2_rn(y0, y1);
                    } else if (cls == 1) {
                        int col = gcol - 2048, kvh = col >> 7, d = col & 127;
                        v0 += bk[col]; v1 += bk[col + 1];
                        float c0 = cosb[(size_t)r * DD + d],     s0 = sinb[(size_t)r * DD + d];
                        float c1 = cosb[(size_t)r * DD + d + 1], s1 = sinb[(size_t)r * DD + d + 1];
                        float y0 = v0 * c0 - v1 * s0;
                        float y1 = v1 * c1 + v0 * s1;
                        *(__half2*)(g_k16 + ((size_t)r * NKV + kvh) * DD + d) = __floats2half2_rn(y0, y1);
                        int bb = r >> 11, sl = r & 2047;
                        int p = pos[sl];
                        *(float2*)(kcache + (((size_t)bb * MAXS + p) * NKV + kvh) * DD + d) =
                            make_float2(y0, y1);
                    } else {
                        int col = gcol - 2560, kvh = col >> 7, d = col & 127;
                        v0 += bv[col]; v1 += bv[col + 1];
                        *(__half2*)(g_v16 + ((size_t)r * NKV + kvh) * DD + d) = __floats2half2_rn(v0, v1);
                        int bb = r >> 11, sl = r & 2047;
                        int p = pos[sl];
                        *(float2*)(vcache + (((size_t)bb * MAXS + p) * NKV + kvh) * DD + d) =
                            make_float2(v0, v1);
                    }
                }
            }
    } else {
        #pragma unroll
        for (int mt = 0; mt < 4; mt++)
            #pragma unroll
            for (int nt = 0; nt < 8; nt++) {
                int cl = wn * 64 + nt * 8 + 2 * c;
                #pragma unroll
                for (int hf = 0; hf < 2; hf++) {
                    int r = rowblk + wm * 64 + mt * 16 + g + hf * 8;
                    const float* res = resid + (size_t)r * 2048 + colblk + cl;
                    float v0 = acc[mt][nt][hf * 2 + 0] + res[0];
                    float v1 = acc[mt][nt][hf * 2 + 1] + res[1];
                    *(float2*)(outf + (size_t)r * 2048 + colblk + cl) = make_float2(v0, v1);
                }
            }
    }
}

// ---------------- FA2 attention: BM=128, BN=128, D=128, fp16 HMMA ----------------
#define AKSTR 272
#define QB (128*AKSTR)
#define KVB (128*AKSTR)
#define KOFF(s) (QB + (s)*2*KVB)
#define VOFF(s) (QB + (s)*2*KVB + KVB)
#define ASMEM (QB + 4*KVB)             // 174080

__global__ void __launch_bounds__(256) attn16_kernel()
{
    extern __shared__ char smem[];
    uint32_t sb = smem_u32(smem);
    const int tid = threadIdx.x, lane = tid & 31, w = tid >> 5;
    const int g = lane >> 2, c = lane & 3;
    const int lq = lane & 15, lh = lane >> 4;
    const int idx = blockIdx.x;
    const int qt = 15 - (idx >> 5);
    const int bh = idx & 31, b = bh >> 4, h = bh & 15, kvh = h >> 2;

    #pragma unroll
    for (int rep = 0; rep < 8; rep++) {
        int lin = rep * 256 + tid;
        int row = lin >> 4, sec = lin & 15;
        cp16(sb + (uint32_t)(row * AKSTR + sec * 16),
             g_q16 + (((size_t)(b * SS + qt * 128 + row)) * NH + h) * DD + sec * 8);
        cp16(sb + (uint32_t)(KOFF(0) + row * AKSTR + sec * 16),
             g_k16 + (((size_t)(b * SS + row)) * NKV + kvh) * DD + sec * 8);
        cp16(sb + (uint32_t)(VOFF(0) + row * AKSTR + sec * 16),
             g_v16 + (((size_t)(b * SS + row)) * NKV + kvh) * DD + sec * 8);
    }
    CP_COMMIT();

    uint32_t qf[8][4];
    float O[16][4];
    #pragma unroll
    for (int j = 0; j < 16; j++)
        #pragma unroll
        for (int r = 0; r < 4; r++) O[j][r] = 0.f;
    float ls[4] = {0.f, 0.f, 0.f, 0.f};
    float m0 = -1e30f, m1 = -1e30f;
    const uint32_t ONE2 = 0x3C003C00u;

    const int nkt = qt + 1;
    for (int kt = 0; kt < nkt; kt++) {
        if (kt + 1 < nkt) {
            int st = (kt + 1) & 1;
            #pragma unroll
            for (int rep = 0; rep < 8; rep++) {
                int lin = rep * 256 + tid;
                int row = lin >> 4, sec = lin & 15;
                int s = (kt + 1) * 128 + row;
                cp16(sb + (uint32_t)(KOFF(st) + row * AKSTR + sec * 16),
                     g_k16 + (((size_t)(b * SS + s)) * NKV + kvh) * DD + sec * 8);
                cp16(sb + (uint32_t)(VOFF(st) + row * AKSTR + sec * 16),
                     g_v16 + (((size_t)(b * SS + s)) * NKV + kvh) * DD + sec * 8);
            }
            CP_COMMIT();
            CP_WAIT(1);
        } else {
            CP_WAIT(0);
        }
        __syncthreads();

        if (kt == 0) {
            #pragma unroll
            for (int kk = 0; kk < 8; kk++)
                ldsm4(qf[kk], sb + (uint32_t)((w * 16 + lq) * AKSTR + (kk * 16 + 8 * lh) * 2));
        }
        int cur = kt & 1;

        float s[16][4];
        #pragma unroll
        for (int j = 0; j < 16; j++)
            #pragma unroll
            for (int r = 0; r < 4; r++) s[j][r] = 0.f;
        #pragma unroll
        for (int kk = 0; kk < 8; kk++) {
            #pragma unroll
            for (int j2 = 0; j2 < 8; j2++) {
                uint32_t r[4];
                ldsm4(r, sb + (uint32_t)(KOFF(cur) + (j2 * 16 + lq) * AKSTR
                                         + (kk * 16 + 8 * lh) * 2));
                uint32_t b0[2] = { r[0], r[2] }, b1[2] = { r[1], r[3] };
                mma16816(s[2 * j2], qf[kk], b0);
                mma16816(s[2 * j2 + 1], qf[kk], b1);
            }
        }
        if (kt == qt) {
            int row0 = qt * 128 + w * 16 + g;
            #pragma unroll
            for (int j = 0; j < 16; j++) {
                int col = kt * 128 + j * 8 + 2 * c;
                if (col > row0)         s[j][0] = -1e30f;
                if (col + 1 > row0)     s[j][1] = -1e30f;
                if (col > row0 + 8)     s[j][2] = -1e30f;
                if (col + 1 > row0 + 8) s[j][3] = -1e30f;
            }
        }
        float r0 = -1e30f, r1 = -1e30f;
        #pragma unroll
        for (int j = 0; j < 16; j++) {
            r0 = fmaxf(r0, fmaxf(s[j][0], s[j][1]));
            r1 = fmaxf(r1, fmaxf(s[j][2], s[j][3]));
        }
        r0 = fmaxf(r0, __shfl_xor_sync(0xffffffffu, r0, 1));
        r0 = fmaxf(r0, __shfl_xor_sync(0xffffffffu, r0, 2));
        r1 = fmaxf(r1, __shfl_xor_sync(0xffffffffu, r1, 1));
        r1 = fmaxf(r1, __shfl_xor_sync(0xffffffffu, r1, 2));
        float mn0 = fmaxf(m0, r0), mn1 = fmaxf(m1, r1);
        float a0 = __expf(m0 - mn0), a1 = __expf(m1 - mn1);
        m0 = mn0; m1 = mn1;
        float nl0 = mn0 * L2E, nl1 = mn1 * L2E;

        uint32_t ph[16][2];
        #pragma unroll
        for (int j = 0; j < 16; j++) {
            ph[j][0] = expx2_h2(fmaf(s[j][0], L2E, -nl0), fmaf(s[j][1], L2E, -nl0));
            ph[j][1] = expx2_h2(fmaf(s[j][2], L2E, -nl1), fmaf(s[j][3], L2E, -nl1));
        }
        #pragma unroll
        for (int j = 0; j < 16; j++) {
            O[j][0] *= a0; O[j][1] *= a0;
            O[j][2] *= a1; O[j][3] *= a1;
        }
        ls[0] *= a0; ls[1] *= a0; ls[2] *= a1; ls[3] *= a1;

        uint32_t bone[2] = { ONE2, ONE2 };
        #pragma unroll
        for (int kk2 = 0; kk2 < 8; kk2++) {
            uint32_t pa[4] = { ph[2 * kk2][0], ph[2 * kk2][1],
                               ph[2 * kk2 + 1][0], ph[2 * kk2 + 1][1] };
            mma16816(ls, pa, bone);
            #pragma unroll
            for (int j2 = 0; j2 < 8; j2++) {
                uint32_t r[4];
                ldsm4t(r, sb + (uint32_t)(VOFF(cur) + (kk2 * 16 + lq) * AKSTR
                                          + (j2 * 16 + 8 * lh) * 2));
                mma16816(O[2 * j2], pa, r);
                mma16816(O[2 * j2 + 1], pa, r + 2);
            }
        }
        __syncthreads();
    }

    float inv0 = 1.f / ls[0], inv1 = 1.f / ls[2];
    int row0 = qt * 128 + w * 16 + g;
    __half* op0 = g_ctx16 + (((size_t)(b * SS + row0)) * NH + h) * DD;
    __half* op1 = g_ctx16 + (((size_t)(b * SS + row0 + 8)) * NH + h) * DD;
    #pragma unroll
    for (int j = 0; j < 16; j++) {
        int col = j * 8 + 2 * c;
        *(__half2*)(op0 + col) = __floats2half2_rn(O[j][0] * inv0, O[j][1] * inv0);
        *(__half2*)(op1 + col) = __floats2half2_rn(O[j][2] * inv1, O[j][3] * inv1);
    }
}

// ---------------- launch ----------------
extern "C" void kernel_launch(void* const* d_in, const int* in_sizes, int n_in,
                              void* d_out, int out_size)
{
    const float* hidden = (const float*)d_in[0];
    const float* lnw    = (const float*)d_in[1];
    const float* Wq     = (const float*)d_in[2];
    const float* bq     = (const float*)d_in[3];
    const float* Wk     = (const float*)d_in[4];
    const float* bk     = (const float*)d_in[5];
    const float* Wv     = (const float*)d_in[6];
    const float* bv     = (const float*)d_in[7];
    const float* Wo     = (const float*)d_in[8];
    const float* cosb   = (const float*)d_in[9];
    const float* sinb   = (const float*)d_in[10];
    const float* kc_in  = (const float*)d_in[11];
    const float* vc_in  = (const float*)d_in[12];
    const int*   pos    = (const int*)d_in[13];

    float* out    = (float*)d_out;
    float* kc_out = out + (size_t)BB * SS * HIDN;
    float* vc_out = kc_out + (size_t)BB * MAXS * NKV * DD;

    __half *ph, *pctx, *pw, *pwo;
    cudaGetSymbolAddress((void**)&ph,   g_h16);
    cudaGetSymbolAddress((void**)&pctx, g_ctx16);
    cudaGetSymbolAddress((void**)&pw,   g_w16);
    cudaGetSymbolAddress((void**)&pwo,  g_wo16);

    const int M = BB * SS;   // 4096

    // 0. weight prep
    transpose_qkv_kernel<<<dim3(64, 96), 256>>>(Wq, Wk, Wv, pw);
    transpose_wo_kernel<<<dim3(64, 64), 256>>>(Wo, pwo);

    // 1. caches base copy
    cudaMemcpyAsync(kc_out, kc_in, (size_t)BB * MAXS * NKV * DD * sizeof(float),
                    cudaMemcpyDeviceToDevice);
    cudaMemcpyAsync(vc_out, vc_in, (size_t)BB * MAXS * NKV * DD * sizeof(float),
                    cudaMemcpyDeviceToDevice);

    // 2. RMSNorm -> fp16
    rmsnorm16_kernel<<<M, 256>>>(hidden, lnw, ph);

    // 3. fused QKV GEMM + bias + RoPE + qscale + cache writes
    cudaFuncSetAttribute(h16_gemm_kernel<0>, cudaFuncAttributeMaxDynamicSharedMemorySize, GSMEM);
    h16_gemm_kernel<0><<<dim3(12, 32), 256, GSMEM>>>(
        ph, pw, bq, bk, bv, nullptr, cosb, sinb, pos, kc_out, vc_out, nullptr);

    // 4. attention
    cudaFuncSetAttribute(attn16_kernel, cudaFuncAttributeMaxDynamicSharedMemorySize, ASMEM);
    attn16_kernel<<<512, 256, ASMEM>>>();

    // 5. Wo GEMM + residual
    cudaFuncSetAttribute(h16_gemm_kernel<1>, cudaFuncAttributeMaxDynamicSharedMemorySize, GSMEM);
    h16_gemm_kernel<1><<<dim3(8, 32), 256, GSMEM>>>(
        pctx, pwo, nullptr, nullptr, nullptr, hidden, nullptr, nullptr, nullptr,
        nullptr, nullptr, out);
}

// round 16
// speedup vs baseline: 1.1856x; 1.1856x over previous
#include <cuda_runtime.h>
#include <cuda_fp16.h>
#include <math.h>
#include <stdint.h>

#define BB   2
#define SS   2048
#define HIDN 2048
#define NH   16
#define NKV  4
#define DD   128
#define MAXS 4096
#define GEMM_K 2048
#define QSCALE 0.08838834764831845f
#define L2E 1.4426950408889634f

// ---------------- scratch ----------------
__device__ __half g_h16 [(size_t)BB*SS*GEMM_K];
__device__ __half g_q16 [(size_t)BB*SS*NH*DD];
__device__ __half g_k16 [(size_t)BB*SS*NKV*DD];
__device__ __half g_v16 [(size_t)BB*SS*NKV*DD];
__device__ __half g_ctx16[(size_t)BB*SS*NH*DD];
__device__ __half g_w16 [(size_t)3072*GEMM_K];
__device__ __half g_wo16[(size_t)2048*GEMM_K];

// ---------------- helpers ----------------
__device__ __forceinline__ uint32_t smem_u32(const void* p) {
    uint32_t a;
    asm("{ .reg .u64 t; cvta.to.shared.u64 t, %1; cvt.u32.u64 %0, t; }" : "=r"(a) : "l"(p));
    return a;
}
__device__ __forceinline__ void cp16(uint32_t dst, const void* src) {
    asm volatile("cp.async.cg.shared.global [%0], [%1], 16;" :: "r"(dst), "l"(src));
}
#define CP_COMMIT() asm volatile("cp.async.commit_group;" ::: "memory")
#define CP_WAIT(n)  asm volatile("cp.async.wait_group %0;" :: "n"(n) : "memory")

__device__ __forceinline__ void ldsm4(uint32_t* r, uint32_t addr) {
    asm volatile("ldmatrix.sync.aligned.m8n8.x4.shared.b16 {%0,%1,%2,%3}, [%4];"
        : "=r"(r[0]), "=r"(r[1]), "=r"(r[2]), "=r"(r[3]) : "r"(addr));
}
__device__ __forceinline__ void ldsm4t(uint32_t* r, uint32_t addr) {
    asm volatile("ldmatrix.sync.aligned.m8n8.x4.trans.shared.b16 {%0,%1,%2,%3}, [%4];"
        : "=r"(r[0]), "=r"(r[1]), "=r"(r[2]), "=r"(r[3]) : "r"(addr));
}
__device__ __forceinline__ void mma16816(float* d, const uint32_t* a, const uint32_t* b) {
    asm volatile(
        "mma.sync.aligned.m16n8k16.row.col.f32.f16.f16.f32 "
        "{%0,%1,%2,%3}, {%4,%5,%6,%7}, {%8,%9}, {%0,%1,%2,%3};"
        : "+f"(d[0]), "+f"(d[1]), "+f"(d[2]), "+f"(d[3])
        : "r"(a[0]), "r"(a[1]), "r"(a[2]), "r"(a[3]), "r"(b[0]), "r"(b[1]));
}
__device__ __forceinline__ uint32_t expx2_h2(float t0, float t1) {
    uint32_t h;
    asm("cvt.rn.f16x2.f32 %0, %1, %2;" : "=r"(h) : "f"(t1), "f"(t0));
    asm("ex2.approx.f16x2 %0, %0;" : "+r"(h));
    return h;
}

// ---------------- RMSNorm -> fp16 ----------------
__global__ void rmsnorm16_kernel(const float* __restrict__ x,
                                 const float* __restrict__ w,
                                 __half* __restrict__ h)
{
    int row = blockIdx.x;
    const float* xr = x + (size_t)row * HIDN;
    float ss = 0.f;
    for (int i = threadIdx.x; i < HIDN; i += blockDim.x) { float v = xr[i]; ss += v * v; }
    __shared__ float sred[32];
    #pragma unroll
    for (int o = 16; o > 0; o >>= 1) ss += __shfl_xor_sync(0xffffffffu, ss, o);
    if ((threadIdx.x & 31) == 0) sred[threadIdx.x >> 5] = ss;
    __syncthreads();
    if (threadIdx.x < 32) {
        float v = (threadIdx.x < (blockDim.x >> 5)) ? sred[threadIdx.x] : 0.f;
        #pragma unroll
        for (int o = 16; o > 0; o >>= 1) v += __shfl_xor_sync(0xffffffffu, v, o);
        if (threadIdx.x == 0) sred[0] = v;
    }
    __syncthreads();
    float rstd = rsqrtf(sred[0] / (float)HIDN + 1e-6f);
    for (int i = threadIdx.x; i < HIDN; i += blockDim.x)
        h[(size_t)row * HIDN + i] = __float2half_rn(xr[i] * rstd * w[i]);
}

// ---------------- weight transposes ----------------
__global__ void transpose_qkv_kernel(const float* __restrict__ Wq,
                                     const float* __restrict__ Wk,
                                     const float* __restrict__ Wv,
                                     __half* __restrict__ o)
{
    __shared__ float t[32][33];
    int k0 = blockIdx.x * 32, ng0 = blockIdx.y * 32;
    const float* W; int Nsrc; int nsrc0;
    if (ng0 < 2048)      { W = Wq; Nsrc = 2048; nsrc0 = ng0; }
    else if (ng0 < 2560) { W = Wk; Nsrc = 512;  nsrc0 = ng0 - 2048; }
    else                 { W = Wv; Nsrc = 512;  nsrc0 = ng0 - 2560; }
    int tx = threadIdx.x & 31, ty = threadIdx.x >> 5;
    #pragma unroll
    for (int i = 0; i < 4; i++)
        t[ty + i * 8][tx] = W[(size_t)(k0 + ty + i * 8) * Nsrc + nsrc0 + tx];
    __syncthreads();
    #pragma unroll
    for (int i = 0; i < 4; i++)
        o[(size_t)(ng0 + ty + i * 8) * GEMM_K + k0 + tx] = __float2half_rn(t[tx][ty + i * 8]);
}

__global__ void transpose_wo_kernel(const float* __restrict__ W, __half* __restrict__ o)
{
    __shared__ float t[32][33];
    int k0 = blockIdx.x * 32, n0 = blockIdx.y * 32;
    int tx = threadIdx.x & 31, ty = threadIdx.x >> 5;
    #pragma unroll
    for (int i = 0; i < 4; i++)
        t[ty + i * 8][tx] = W[(size_t)(k0 + ty + i * 8) * 2048 + n0 + tx];
    __syncthreads();
    #pragma unroll
    for (int i = 0; i < 4; i++)
        o[(size_t)(n0 + ty + i * 8) * GEMM_K + k0 + tx] = __float2half_rn(t[tx][ty + i * 8]);
}

// ---------------- fp16 HMMA GEMM: CTA 128x128, warp 64x32, BK=64, 3 stages ----------------
// One barrier per chunk: iter kc writes stage (kc+2)%3, which was last read in
// iter kc-1 — every thread passed this iteration's barrier only after finishing
// that compute, so the write is safe. 2 chunks of cp.async in flight.
#define KSTRB 144
#define ATILE (128*KSTRB)              // 18432
#define STAGE (2*ATILE)                // 36864 (A tile + B tile)
#define NSTG  3
#define GSMEM (NSTG*STAGE)             // 110592  -> 2 CTAs/SM

template<int MODE>   // 0 = QKV (bias + rope + cache), 1 = Wo (residual, fp32 out)
__global__ void __launch_bounds__(256, 2) h16_gemm_kernel(
    const __half* __restrict__ A, const __half* __restrict__ Bm,
    const float* __restrict__ bq, const float* __restrict__ bk, const float* __restrict__ bv,
    const float* __restrict__ resid,
    const float* __restrict__ cosb, const float* __restrict__ sinb,
    const int* __restrict__ pos,
    float* __restrict__ kcache, float* __restrict__ vcache,
    float* __restrict__ outf)
{
    extern __shared__ char smem[];
    uint32_t sb = smem_u32(smem);
    const int tid = threadIdx.x, lane = tid & 31, wid = tid >> 5;
    const int wm = wid >> 2, wn = wid & 3;
    const int g = lane >> 2, c = lane & 3;
    const int lq = lane & 15, lh = lane >> 4;
    const int rowblk = blockIdx.y * 128, colblk = blockIdx.x * 128;

    // cp.async plan: 8 x 16B per thread (4 A + 4 B)
    const __half* gsrc[8];
    uint32_t soff[8];
    #pragma unroll
    for (int rep = 0; rep < 8; rep++) {
        int lin = (rep & 3) * 256 + tid;
        int row = lin >> 3, sec = lin & 7;
        if (rep < 4) {
            gsrc[rep] = A + (size_t)(rowblk + row) * GEMM_K + sec * 8;
            soff[rep] = (uint32_t)(row * KSTRB + sec * 16);
        } else {
            gsrc[rep] = Bm + (size_t)(colblk + row) * GEMM_K + sec * 8;
            soff[rep] = (uint32_t)(ATILE + row * KSTRB + sec * 16);
        }
    }

    float acc[4][4][4];
    #pragma unroll
    for (int mt = 0; mt < 4; mt++)
        #pragma unroll
        for (int nt = 0; nt < 4; nt++)
            #pragma unroll
            for (int r = 0; r < 4; r++) acc[mt][nt][r] = 0.f;

    // prologue: chunks 0,1 -> stages 0,1
    #pragma unroll
    for (int st = 0; st < 2; st++) {
        uint32_t stb = sb + (uint32_t)(st * STAGE);
        #pragma unroll
        for (int rep = 0; rep < 8; rep++) cp16(stb + soff[rep], gsrc[rep] + st * 64);
        CP_COMMIT();
    }

    const int NCH = GEMM_K / 64;   // 32
    for (int kc = 0; kc < NCH; kc++) {
        CP_WAIT(1);                // chunk kc resident
        __syncthreads();
        if (kc + 2 < NCH) {
            uint32_t stb = sb + (uint32_t)(((kc + 2) % NSTG) * STAGE);
            #pragma unroll
            for (int rep = 0; rep < 8; rep++)
                cp16(stb + soff[rep], gsrc[rep] + (kc + 2) * 64);
        }
        CP_COMMIT();

        uint32_t base = sb + (uint32_t)((kc % NSTG) * STAGE);
        #pragma unroll
        for (int kk = 0; kk < 4; kk++) {
            uint32_t af[4][4], bf[4][2];
            #pragma unroll
            for (int mt = 0; mt < 4; mt++)
                ldsm4(af[mt], base + (uint32_t)((wm * 64 + mt * 16 + lq) * KSTRB
                                                + (kk * 16 + 8 * lh) * 2));
            #pragma unroll
            for (int ntp = 0; ntp < 2; ntp++) {
                uint32_t r[4];
                ldsm4(r, base + (uint32_t)(ATILE + (wn * 32 + ntp * 16 + lq) * KSTRB
                                           + (kk * 16 + 8 * lh) * 2));
                bf[2 * ntp][0] = r[0]; bf[2 * ntp][1] = r[2];
                bf[2 * ntp + 1][0] = r[1]; bf[2 * ntp + 1][1] = r[3];
            }
            #pragma unroll
            for (int mt = 0; mt < 4; mt++)
                #pragma unroll
                for (int nt = 0; nt < 4; nt++) mma16816(acc[mt][nt], af[mt], bf[nt]);
        }
    }

    if (MODE == 0) {
        int cls = (colblk < 2048) ? 0 : (colblk < 2560 ? 1 : 2);
        #pragma unroll
        for (int mt = 0; mt < 4; mt++)
            #pragma unroll
            for (int nt = 0; nt < 4; nt++) {
                int cl = wn * 32 + nt * 8 + 2 * c;
                int gcol = colblk + cl;
                #pragma unroll
                for (int hf = 0; hf < 2; hf++) {
                    int r = rowblk + wm * 64 + mt * 16 + g + hf * 8;
                    float v0 = acc[mt][nt][hf * 2 + 0];
                    float v1 = acc[mt][nt][hf * 2 + 1];
                    if (cls == 0) {
                        int hh = gcol >> 7, d = gcol & 127;
                        v0 += bq[gcol]; v1 += bq[gcol + 1];
                        float c0 = cosb[(size_t)r * DD + d],     s0 = sinb[(size_t)r * DD + d];
                        float c1 = cosb[(size_t)r * DD + d + 1], s1 = sinb[(size_t)r * DD + d + 1];
                        float y0 = (v0 * c0 - v1 * s0) * QSCALE;
                        float y1 = (v1 * c1 + v0 * s1) * QSCALE;
                        *(__half2*)(g_q16 + ((size_t)r * NH + hh) * DD + d) = __floats2half2_rn(y0, y1);
                    } else if (cls == 1) {
                        int col = gcol - 2048, kvh = col >> 7, d = col & 127;
                        v0 += bk[col]; v1 += bk[col + 1];
                        float c0 = cosb[(size_t)r * DD + d],     s0 = sinb[(size_t)r * DD + d];
                        float c1 = cosb[(size_t)r * DD + d + 1], s1 = sinb[(size_t)r * DD + d + 1];
                        float y0 = v0 * c0 - v1 * s0;
                        float y1 = v1 * c1 + v0 * s1;
                        *(__half2*)(g_k16 + ((size_t)r * NKV + kvh) * DD + d) = __floats2half2_rn(y0, y1);
                        int bb = r >> 11, sl = r & 2047;
                        int p = pos[sl];
                        *(float2*)(kcache + (((size_t)bb * MAXS + p) * NKV + kvh) * DD + d) =
                            make_float2(y0, y1);
                    } else {
                        int col = gcol - 2560, kvh = col >> 7, d = col & 127;
                        v0 += bv[col]; v1 += bv[col + 1];
                        *(__half2*)(g_v16 + ((size_t)r * NKV + kvh) * DD + d) = __floats2half2_rn(v0, v1);
                        int bb = r >> 11, sl = r & 2047;
                        int p = pos[sl];
                        *(float2*)(vcache + (((size_t)bb * MAXS + p) * NKV + kvh) * DD + d) =
                            make_float2(v0, v1);
                    }
                }
            }
    } else {
        #pragma unroll
        for (int mt = 0; mt < 4; mt++)
            #pragma unroll
            for (int nt = 0; nt < 4; nt++) {
                int cl = wn * 32 + nt * 8 + 2 * c;
                #pragma unroll
                for (int hf = 0; hf < 2; hf++) {
                    int r = rowblk + wm * 64 + mt * 16 + g + hf * 8;
                    const float* res = resid + (size_t)r * 2048 + colblk + cl;
                    float v0 = acc[mt][nt][hf * 2 + 0] + res[0];
                    float v1 = acc[mt][nt][hf * 2 + 1] + res[1];
                    *(float2*)(outf + (size_t)r * 2048 + colblk + cl) = make_float2(v0, v1);
                }
            }
    }
}

// ---------------- FA2 attention: BM=128, BN=128, D=128, fp16 HMMA ----------------
#define AKSTR 272
#define QB (128*AKSTR)
#define KVB (128*AKSTR)
#define KOFF(s) (QB + (s)*2*KVB)
#define VOFF(s) (QB + (s)*2*KVB + KVB)
#define ASMEM (QB + 4*KVB)             // 174080

__global__ void __launch_bounds__(256) attn16_kernel()
{
    extern __shared__ char smem[];
    uint32_t sb = smem_u32(smem);
    const int tid = threadIdx.x, lane = tid & 31, w = tid >> 5;
    const int g = lane >> 2, c = lane & 3;
    const int lq = lane & 15, lh = lane >> 4;
    const int idx = blockIdx.x;
    const int qt = 15 - (idx >> 5);
    const int bh = idx & 31, b = bh >> 4, h = bh & 15, kvh = h >> 2;

    #pragma unroll
    for (int rep = 0; rep < 8; rep++) {
        int lin = rep * 256 + tid;
        int row = lin >> 4, sec = lin & 15;
        cp16(sb + (uint32_t)(row * AKSTR + sec * 16),
             g_q16 + (((size_t)(b * SS + qt * 128 + row)) * NH + h) * DD + sec * 8);
        cp16(sb + (uint32_t)(KOFF(0) + row * AKSTR + sec * 16),
             g_k16 + (((size_t)(b * SS + row)) * NKV + kvh) * DD + sec * 8);
        cp16(sb + (uint32_t)(VOFF(0) + row * AKSTR + sec * 16),
             g_v16 + (((size_t)(b * SS + row)) * NKV + kvh) * DD + sec * 8);
    }
    CP_COMMIT();

    uint32_t qf[8][4];
    float O[16][4];
    #pragma unroll
    for (int j = 0; j < 16; j++)
        #pragma unroll
        for (int r = 0; r < 4; r++) O[j][r] = 0.f;
    float ls[4] = {0.f, 0.f, 0.f, 0.f};
    float m0 = -1e30f, m1 = -1e30f;
    const uint32_t ONE2 = 0x3C003C00u;

    const int nkt = qt + 1;
    for (int kt = 0; kt < nkt; kt++) {
        if (kt + 1 < nkt) {
            int st = (kt + 1) & 1;
            #pragma unroll
            for (int rep = 0; rep < 8; rep++) {
                int lin = rep * 256 + tid;
                int row = lin >> 4, sec = lin & 15;
                int s = (kt + 1) * 128 + row;
                cp16(sb + (uint32_t)(KOFF(st) + row * AKSTR + sec * 16),
                     g_k16 + (((size_t)(b * SS + s)) * NKV + kvh) * DD + sec * 8);
                cp16(sb + (uint32_t)(VOFF(st) + row * AKSTR + sec * 16),
                     g_v16 + (((size_t)(b * SS + s)) * NKV + kvh) * DD + sec * 8);
            }
            CP_COMMIT();
            CP_WAIT(1);
        } else {
            CP_WAIT(0);
        }
        __syncthreads();

        if (kt == 0) {
            #pragma unroll
            for (int kk = 0; kk < 8; kk++)
                ldsm4(qf[kk], sb + (uint32_t)((w * 16 + lq) * AKSTR + (kk * 16 + 8 * lh) * 2));
        }
        int cur = kt & 1;

        float s[16][4];
        #pragma unroll
        for (int j = 0; j < 16; j++)
            #pragma unroll
            for (int r = 0; r < 4; r++) s[j][r] = 0.f;
        #pragma unroll
        for (int kk = 0; kk < 8; kk++) {
            #pragma unroll
            for (int j2 = 0; j2 < 8; j2++) {
                uint32_t r[4];
                ldsm4(r, sb + (uint32_t)(KOFF(cur) + (j2 * 16 + lq) * AKSTR
                                         + (kk * 16 + 8 * lh) * 2));
                uint32_t b0[2] = { r[0], r[2] }, b1[2] = { r[1], r[3] };
                mma16816(s[2 * j2], qf[kk], b0);
                mma16816(s[2 * j2 + 1], qf[kk], b1);
            }
        }
        if (kt == qt) {
            int row0 = qt * 128 + w * 16 + g;
            #pragma unroll
            for (int j = 0; j < 16; j++) {
                int col = kt * 128 + j * 8 + 2 * c;
                if (col > row0)         s[j][0] = -1e30f;
                if (col + 1 > row0)     s[j][1] = -1e30f;
                if (col > row0 + 8)     s[j][2] = -1e30f;
                if (col + 1 > row0 + 8) s[j][3] = -1e30f;
            }
        }
        float r0 = -1e30f, r1 = -1e30f;
        #pragma unroll
        for (int j = 0; j < 16; j++) {
            r0 = fmaxf(r0, fmaxf(s[j][0], s[j][1]));
            r1 = fmaxf(r1, fmaxf(s[j][2], s[j][3]));
        }
        r0 = fmaxf(r0, __shfl_xor_sync(0xffffffffu, r0, 1));
        r0 = fmaxf(r0, __shfl_xor_sync(0xffffffffu, r0, 2));
        r1 = fmaxf(r1, __shfl_xor_sync(0xffffffffu, r1, 1));
        r1 = fmaxf(r1, __shfl_xor_sync(0xffffffffu, r1, 2));
        float mn0 = fmaxf(m0, r0), mn1 = fmaxf(m1, r1);
        float a0 = __expf(m0 - mn0), a1 = __expf(m1 - mn1);
        m0 = mn0; m1 = mn1;
        float nl0 = mn0 * L2E, nl1 = mn1 * L2E;

        uint32_t ph[16][2];
        #pragma unroll
        for (int j = 0; j < 16; j++) {
            ph[j][0] = expx2_h2(fmaf(s[j][0], L2E, -nl0), fmaf(s[j][1], L2E, -nl0));
            ph[j][1] = expx2_h2(fmaf(s[j][2], L2E, -nl1), fmaf(s[j][3], L2E, -nl1));
        }
        #pragma unroll
        for (int j = 0; j < 16; j++) {
            O[j][0] *= a0; O[j][1] *= a0;
            O[j][2] *= a1; O[j][3] *= a1;
        }
        ls[0] *= a0; ls[1] *= a0; ls[2] *= a1; ls[3] *= a1;

        uint32_t bone[2] = { ONE2, ONE2 };
        #pragma unroll
        for (int kk2 = 0; kk2 < 8; kk2++) {
            uint32_t pa[4] = { ph[2 * kk2][0], ph[2 * kk2][1],
                               ph[2 * kk2 + 1][0], ph[2 * kk2 + 1][1] };
            mma16816(ls, pa, bone);
            #pragma unroll
            for (int j2 = 0; j2 < 8; j2++) {
                uint32_t r[4];
                ldsm4t(r, sb + (uint32_t)(VOFF(cur) + (kk2 * 16 + lq) * AKSTR
                                          + (j2 * 16 + 8 * lh) * 2));
                mma16816(O[2 * j2], pa, r);
                mma16816(O[2 * j2 + 1], pa, r + 2);
            }
        }
        __syncthreads();
    }

    float inv0 = 1.f / ls[0], inv1 = 1.f / ls[2];
    int row0 = qt * 128 + w * 16 + g;
    __half* op0 = g_ctx16 + (((size_t)(b * SS + row0)) * NH + h) * DD;
    __half* op1 = g_ctx16 + (((size_t)(b * SS + row0 + 8)) * NH + h) * DD;
    #pragma unroll
    for (int j = 0; j < 16; j++) {
        int col = j * 8 + 2 * c;
        *(__half2*)(op0 + col) = __floats2half2_rn(O[j][0] * inv0, O[j][1] * inv0);
        *(__half2*)(op1 + col) = __floats2half2_rn(O[j][2] * inv1, O[j][3] * inv1);
    }
}

// ---------------- launch ----------------
extern "C" void kernel_launch(void* const* d_in, const int* in_sizes, int n_in,
                              void* d_out, int out_size)
{
    const float* hidden = (const float*)d_in[0];
    const float* lnw    = (const float*)d_in[1];
    const float* Wq     = (const float*)d_in[2];
    const float* bq     = (const float*)d_in[3];
    const float* Wk     = (const float*)d_in[4];
    const float* bk     = (const float*)d_in[5];
    const float* Wv     = (const float*)d_in[6];
    const float* bv     = (const float*)d_in[7];
    const float* Wo     = (const float*)d_in[8];
    const float* cosb   = (const float*)d_in[9];
    const float* sinb   = (const float*)d_in[10];
    const float* kc_in  = (const float*)d_in[11];
    const float* vc_in  = (const float*)d_in[12];
    const int*   pos    = (const int*)d_in[13];

    float* out    = (float*)d_out;
    float* kc_out = out + (size_t)BB * SS * HIDN;
    float* vc_out = kc_out + (size_t)BB * MAXS * NKV * DD;

    __half *ph, *pctx, *pw, *pwo;
    cudaGetSymbolAddress((void**)&ph,   g_h16);
    cudaGetSymbolAddress((void**)&pctx, g_ctx16);
    cudaGetSymbolAddress((void**)&pw,   g_w16);
    cudaGetSymbolAddress((void**)&pwo,  g_wo16);

    const int M = BB * SS;   // 4096

    // 0. weight prep
    transpose_qkv_kernel<<<dim3(64, 96), 256>>>(Wq, Wk, Wv, pw);
    transpose_wo_kernel<<<dim3(64, 64), 256>>>(Wo, pwo);

    // 1. caches base copy
    cudaMemcpyAsync(kc_out, kc_in, (size_t)BB * MAXS * NKV * DD * sizeof(float),
                    cudaMemcpyDeviceToDevice);
    cudaMemcpyAsync(vc_out, vc_in, (size_t)BB * MAXS * NKV * DD * sizeof(float),
                    cudaMemcpyDeviceToDevice);

    // 2. RMSNorm -> fp16
    rmsnorm16_kernel<<<M, 256>>>(hidden, lnw, ph);

    // 3. fused QKV GEMM + bias + RoPE + qscale + cache writes
    cudaFuncSetAttribute(h16_gemm_kernel<0>, cudaFuncAttributeMaxDynamicSharedMemorySize, GSMEM);
    h16_gemm_kernel<0><<<dim3(24, 32), 256, GSMEM>>>(
        ph, pw, bq, bk, bv, nullptr, cosb, sinb, pos, kc_out, vc_out, nullptr);

    // 4. attention
    cudaFuncSetAttribute(attn16_kernel, cudaFuncAttributeMaxDynamicSharedMemorySize, ASMEM);
    attn16_kernel<<<512, 256, ASMEM>>>();

    // 5. Wo GEMM + residual
    cudaFuncSetAttribute(h16_gemm_kernel<1>, cudaFuncAttributeMaxDynamicSharedMemorySize, GSMEM);
    h16_gemm_kernel<1><<<dim3(16, 32), 256, GSMEM>>>(
        pctx, pwo, nullptr, nullptr, nullptr, hidden, nullptr, nullptr, nullptr,
        nullptr, nullptr, out);
}

// round 17
// speedup vs baseline: 1.2042x; 1.0157x over previous
#include <cuda_runtime.h>
#include <cuda_fp16.h>
#include <math.h>
#include <stdint.h>

#define BB   2
#define SS   2048
#define HIDN 2048
#define NH   16
#define NKV  4
#define DD   128
#define MAXS 4096
#define GEMM_K 2048
#define QSCALE 0.08838834764831845f
#define L2E 1.4426950408889634f

// ---------------- scratch ----------------
__device__ __half g_h16 [(size_t)BB*SS*GEMM_K];
__device__ __half g_q16 [(size_t)BB*SS*NH*DD];
__device__ __half g_k16 [(size_t)BB*SS*NKV*DD];
__device__ __half g_v16 [(size_t)BB*SS*NKV*DD];
__device__ __half g_ctx16[(size_t)BB*SS*NH*DD];
__device__ __half g_w16 [(size_t)3072*GEMM_K];
__device__ __half g_wo16[(size_t)2048*GEMM_K];

// ---------------- helpers ----------------
__device__ __forceinline__ uint32_t smem_u32(const void* p) {
    uint32_t a;
    asm("{ .reg .u64 t; cvta.to.shared.u64 t, %1; cvt.u32.u64 %0, t; }" : "=r"(a) : "l"(p));
    return a;
}
__device__ __forceinline__ void cp16(uint32_t dst, const void* src) {
    asm volatile("cp.async.cg.shared.global [%0], [%1], 16;" :: "r"(dst), "l"(src));
}
#define CP_COMMIT() asm volatile("cp.async.commit_group;" ::: "memory")
#define CP_WAIT(n)  asm volatile("cp.async.wait_group %0;" :: "n"(n) : "memory")

__device__ __forceinline__ void ldsm4(uint32_t* r, uint32_t addr) {
    asm volatile("ldmatrix.sync.aligned.m8n8.x4.shared.b16 {%0,%1,%2,%3}, [%4];"
        : "=r"(r[0]), "=r"(r[1]), "=r"(r[2]), "=r"(r[3]) : "r"(addr));
}
__device__ __forceinline__ void ldsm4t(uint32_t* r, uint32_t addr) {
    asm volatile("ldmatrix.sync.aligned.m8n8.x4.trans.shared.b16 {%0,%1,%2,%3}, [%4];"
        : "=r"(r[0]), "=r"(r[1]), "=r"(r[2]), "=r"(r[3]) : "r"(addr));
}
__device__ __forceinline__ void mma16816(float* d, const uint32_t* a, const uint32_t* b) {
    asm volatile(
        "mma.sync.aligned.m16n8k16.row.col.f32.f16.f16.f32 "
        "{%0,%1,%2,%3}, {%4,%5,%6,%7}, {%8,%9}, {%0,%1,%2,%3};"
        : "+f"(d[0]), "+f"(d[1]), "+f"(d[2]), "+f"(d[3])
        : "r"(a[0]), "r"(a[1]), "r"(a[2]), "r"(a[3]), "r"(b[0]), "r"(b[1]));
}
__device__ __forceinline__ uint32_t expx2_h2(float t0, float t1) {
    uint32_t h;
    asm("cvt.rn.f16x2.f32 %0, %1, %2;" : "=r"(h) : "f"(t1), "f"(t0));
    asm("ex2.approx.f16x2 %0, %0;" : "+r"(h));
    return h;
}

// ---------------- fused prep: rmsnorm + both transposes + cache base copy ----------------
// block roles by blockIdx.x:
//   [0, 4096)          : rmsnorm row
//   [4096, 10240)      : QKV weight transpose tile (64 x 96 tiles)
//   [10240, 14336)     : Wo weight transpose tile (64 x 64 tiles)
//   [14336, 16384)     : KV-cache base copy (grid-stride float4)
#define PREP_RMS   4096
#define PREP_TQKV  (PREP_RMS + 6144)
#define PREP_TWO   (PREP_TQKV + 4096)
#define PREP_COPY  (PREP_TWO + 2048)

__global__ void __launch_bounds__(256) prep_kernel(
    const float* __restrict__ x, const float* __restrict__ lnw,
    const float* __restrict__ Wq, const float* __restrict__ Wk, const float* __restrict__ Wv,
    const float* __restrict__ Wo,
    const float* __restrict__ kc_in, const float* __restrict__ vc_in,
    float* __restrict__ kc_out, float* __restrict__ vc_out)
{
    int bidx = blockIdx.x;
    if (bidx < PREP_RMS) {
        // ---- RMSNorm row -> fp16 ----
        int row = bidx;
        const float* xr = x + (size_t)row * HIDN;
        float ss = 0.f;
        for (int i = threadIdx.x; i < HIDN; i += 256) { float v = xr[i]; ss += v * v; }
        __shared__ float sred[32];
        #pragma unroll
        for (int o = 16; o > 0; o >>= 1) ss += __shfl_xor_sync(0xffffffffu, ss, o);
        if ((threadIdx.x & 31) == 0) sred[threadIdx.x >> 5] = ss;
        __syncthreads();
        if (threadIdx.x < 32) {
            float v = (threadIdx.x < 8) ? sred[threadIdx.x] : 0.f;
            #pragma unroll
            for (int o = 16; o > 0; o >>= 1) v += __shfl_xor_sync(0xffffffffu, v, o);
            if (threadIdx.x == 0) sred[0] = v;
        }
        __syncthreads();
        float rstd = rsqrtf(sred[0] / (float)HIDN + 1e-6f);
        for (int i = threadIdx.x; i < HIDN; i += 256)
            g_h16[(size_t)row * HIDN + i] = __float2half_rn(xr[i] * rstd * lnw[i]);
    } else if (bidx < PREP_TWO) {
        // ---- weight transpose (QKV or Wo) ----
        __shared__ float t[32][33];
        const float* W; int Nsrc, nsrc0, ng0, k0;
        __half* dst;
        if (bidx < PREP_TQKV) {
            int tt = bidx - PREP_RMS;
            k0 = (tt & 63) * 32; ng0 = (tt >> 6) * 32;
            if (ng0 < 2048)      { W = Wq; Nsrc = 2048; nsrc0 = ng0; }
            else if (ng0 < 2560) { W = Wk; Nsrc = 512;  nsrc0 = ng0 - 2048; }
            else                 { W = Wv; Nsrc = 512;  nsrc0 = ng0 - 2560; }
            dst = g_w16;
        } else {
            int tt = bidx - PREP_TQKV;
            k0 = (tt & 63) * 32; ng0 = (tt >> 6) * 32;
            W = Wo; Nsrc = 2048; nsrc0 = ng0;
            dst = g_wo16;
        }
        int tx = threadIdx.x & 31, ty = threadIdx.x >> 5;
        #pragma unroll
        for (int i = 0; i < 4; i++)
            t[ty + i * 8][tx] = W[(size_t)(k0 + ty + i * 8) * Nsrc + nsrc0 + tx];
        __syncthreads();
        #pragma unroll
        for (int i = 0; i < 4; i++)
            dst[(size_t)(ng0 + ty + i * 8) * GEMM_K + k0 + tx] = __float2half_rn(t[tx][ty + i * 8]);
    } else {
        // ---- KV cache base copy: 2048 blocks x 256 thr x 2 float4 per cache ----
        int tt = bidx - PREP_TWO;                       // 0..2047
        size_t base = ((size_t)tt * 256 + threadIdx.x) * 2;   // float4 index
        const float4* ki = (const float4*)kc_in;
        const float4* vi = (const float4*)vc_in;
        float4* ko = (float4*)kc_out;
        float4* vo = (float4*)vc_out;
        ko[base]     = ki[base];
        ko[base + 1] = ki[base + 1];
        vo[base]     = vi[base];
        vo[base + 1] = vi[base + 1];
    }
}

// ---------------- fp16 HMMA GEMM: CTA 128x128, warp 64x32, BK=64, 3 stages ----------------
#define KSTRB 144
#define ATILE (128*KSTRB)              // 18432
#define STAGE (2*ATILE)                // 36864
#define NSTG  3
#define GSMEM (NSTG*STAGE)             // 110592  -> 2 CTAs/SM

template<int MODE>   // 0 = QKV (bias + rope + cache), 1 = Wo (residual, fp32 out)
__global__ void __launch_bounds__(256, 2) h16_gemm_kernel(
    const __half* __restrict__ A, const __half* __restrict__ Bm,
    const float* __restrict__ bq, const float* __restrict__ bk, const float* __restrict__ bv,
    const float* __restrict__ resid,
    const float* __restrict__ cosb, const float* __restrict__ sinb,
    const int* __restrict__ pos,
    float* __restrict__ kcache, float* __restrict__ vcache,
    float* __restrict__ outf)
{
    extern __shared__ char smem[];
    uint32_t sb = smem_u32(smem);
    const int tid = threadIdx.x, lane = tid & 31, wid = tid >> 5;
    const int wm = wid >> 2, wn = wid & 3;
    const int g = lane >> 2, c = lane & 3;
    const int lq = lane & 15, lh = lane >> 4;
    const int rowblk = blockIdx.y * 128, colblk = blockIdx.x * 128;

    const __half* gsrc[8];
    uint32_t soff[8];
    #pragma unroll
    for (int rep = 0; rep < 8; rep++) {
        int lin = (rep & 3) * 256 + tid;
        int row = lin >> 3, sec = lin & 7;
        if (rep < 4) {
            gsrc[rep] = A + (size_t)(rowblk + row) * GEMM_K + sec * 8;
            soff[rep] = (uint32_t)(row * KSTRB + sec * 16);
        } else {
            gsrc[rep] = Bm + (size_t)(colblk + row) * GEMM_K + sec * 8;
            soff[rep] = (uint32_t)(ATILE + row * KSTRB + sec * 16);
        }
    }

    float acc[4][4][4];
    #pragma unroll
    for (int mt = 0; mt < 4; mt++)
        #pragma unroll
        for (int nt = 0; nt < 4; nt++)
            #pragma unroll
            for (int r = 0; r < 4; r++) acc[mt][nt][r] = 0.f;

    #pragma unroll
    for (int st = 0; st < 2; st++) {
        uint32_t stb = sb + (uint32_t)(st * STAGE);
        #pragma unroll
        for (int rep = 0; rep < 8; rep++) cp16(stb + soff[rep], gsrc[rep] + st * 64);
        CP_COMMIT();
    }

    const int NCH = GEMM_K / 64;   // 32
    for (int kc = 0; kc < NCH; kc++) {
        CP_WAIT(1);
        __syncthreads();
        if (kc + 2 < NCH) {
            uint32_t stb = sb + (uint32_t)(((kc + 2) % NSTG) * STAGE);
            #pragma unroll
            for (int rep = 0; rep < 8; rep++)
                cp16(stb + soff[rep], gsrc[rep] + (kc + 2) * 64);
        }
        CP_COMMIT();

        uint32_t base = sb + (uint32_t)((kc % NSTG) * STAGE);
        #pragma unroll
        for (int kk = 0; kk < 4; kk++) {
            uint32_t af[4][4], bf[4][2];
            #pragma unroll
            for (int mt = 0; mt < 4; mt++)
                ldsm4(af[mt], base + (uint32_t)((wm * 64 + mt * 16 + lq) * KSTRB
                                                + (kk * 16 + 8 * lh) * 2));
            #pragma unroll
            for (int ntp = 0; ntp < 2; ntp++) {
                uint32_t r[4];
                ldsm4(r, base + (uint32_t)(ATILE + (wn * 32 + ntp * 16 + lq) * KSTRB
                                           + (kk * 16 + 8 * lh) * 2));
                bf[2 * ntp][0] = r[0]; bf[2 * ntp][1] = r[2];
                bf[2 * ntp + 1][0] = r[1]; bf[2 * ntp + 1][1] = r[3];
            }
            #pragma unroll
            for (int mt = 0; mt < 4; mt++)
                #pragma unroll
                for (int nt = 0; nt < 4; nt++) mma16816(acc[mt][nt], af[mt], bf[nt]);
        }
    }

    if (MODE == 0) {
        int cls = (colblk < 2048) ? 0 : (colblk < 2560 ? 1 : 2);
        #pragma unroll
        for (int mt = 0; mt < 4; mt++)
            #pragma unroll
            for (int nt = 0; nt < 4; nt++) {
                int cl = wn * 32 + nt * 8 + 2 * c;
                int gcol = colblk + cl;
                #pragma unroll
                for (int hf = 0; hf < 2; hf++) {
                    int r = rowblk + wm * 64 + mt * 16 + g + hf * 8;
                    float v0 = acc[mt][nt][hf * 2 + 0];
                    float v1 = acc[mt][nt][hf * 2 + 1];
                    if (cls == 0) {
                        int hh = gcol >> 7, d = gcol & 127;
                        v0 += bq[gcol]; v1 += bq[gcol + 1];
                        float c0 = cosb[(size_t)r * DD + d],     s0 = sinb[(size_t)r * DD + d];
                        float c1 = cosb[(size_t)r * DD + d + 1], s1 = sinb[(size_t)r * DD + d + 1];
                        float y0 = (v0 * c0 - v1 * s0) * QSCALE;
                        float y1 = (v1 * c1 + v0 * s1) * QSCALE;
                        *(__half2*)(g_q16 + ((size_t)r * NH + hh) * DD + d) = __floats2half2_rn(y0, y1);
                    } else if (cls == 1) {
                        int col = gcol - 2048, kvh = col >> 7, d = col & 127;
                        v0 += bk[col]; v1 += bk[col + 1];
                        float c0 = cosb[(size_t)r * DD + d],     s0 = sinb[(size_t)r * DD + d];
                        float c1 = cosb[(size_t)r * DD + d + 1], s1 = sinb[(size_t)r * DD + d + 1];
                        float y0 = v0 * c0 - v1 * s0;
                        float y1 = v1 * c1 + v0 * s1;
                        *(__half2*)(g_k16 + ((size_t)r * NKV + kvh) * DD + d) = __floats2half2_rn(y0, y1);
                        int bb = r >> 11, sl = r & 2047;
                        int p = pos[sl];
                        *(float2*)(kcache + (((size_t)bb * MAXS + p) * NKV + kvh) * DD + d) =
                            make_float2(y0, y1);
                    } else {
                        int col = gcol - 2560, kvh = col >> 7, d = col & 127;
                        v0 += bv[col]; v1 += bv[col + 1];
                        *(__half2*)(g_v16 + ((size_t)r * NKV + kvh) * DD + d) = __floats2half2_rn(v0, v1);
                        int bb = r >> 11, sl = r & 2047;
                        int p = pos[sl];
                        *(float2*)(vcache + (((size_t)bb * MAXS + p) * NKV + kvh) * DD + d) =
                            make_float2(v0, v1);
                    }
                }
            }
    } else {
        #pragma unroll
        for (int mt = 0; mt < 4; mt++)
            #pragma unroll
            for (int nt = 0; nt < 4; nt++) {
                int cl = wn * 32 + nt * 8 + 2 * c;
                #pragma unroll
                for (int hf = 0; hf < 2; hf++) {
                    int r = rowblk + wm * 64 + mt * 16 + g + hf * 8;
                    const float* res = resid + (size_t)r * 2048 + colblk + cl;
                    float v0 = acc[mt][nt][hf * 2 + 0] + res[0];
                    float v1 = acc[mt][nt][hf * 2 + 1] + res[1];
                    *(float2*)(outf + (size_t)r * 2048 + colblk + cl) = make_float2(v0, v1);
                }
            }
    }
}

// ---------------- FA2 attention: BM=128, BN=128, D=128, fp16 HMMA ----------------
#define AKSTR 272
#define QB (128*AKSTR)
#define KVB (128*AKSTR)
#define KOFF(s) (QB + (s)*2*KVB)
#define VOFF(s) (QB + (s)*2*KVB + KVB)
#define ASMEM (QB + 4*KVB)             // 174080

__global__ void __launch_bounds__(256) attn16_kernel()
{
    extern __shared__ char smem[];
    uint32_t sb = smem_u32(smem);
    const int tid = threadIdx.x, lane = tid & 31, w = tid >> 5;
    const int g = lane >> 2, c = lane & 3;
    const int lq = lane & 15, lh = lane >> 4;
    const int idx = blockIdx.x;
    const int qt = 15 - (idx >> 5);
    const int bh = idx & 31, b = bh >> 4, h = bh & 15, kvh = h >> 2;

    #pragma unroll
    for (int rep = 0; rep < 8; rep++) {
        int lin = rep * 256 + tid;
        int row = lin >> 4, sec = lin & 15;
        cp16(sb + (uint32_t)(row * AKSTR + sec * 16),
             g_q16 + (((size_t)(b * SS + qt * 128 + row)) * NH + h) * DD + sec * 8);
        cp16(sb + (uint32_t)(KOFF(0) + row * AKSTR + sec * 16),
             g_k16 + (((size_t)(b * SS + row)) * NKV + kvh) * DD + sec * 8);
        cp16(sb + (uint32_t)(VOFF(0) + row * AKSTR + sec * 16),
             g_v16 + (((size_t)(b * SS + row)) * NKV + kvh) * DD + sec * 8);
    }
    CP_COMMIT();

    uint32_t qf[8][4];
    float O[16][4];
    #pragma unroll
    for (int j = 0; j < 16; j++)
        #pragma unroll
        for (int r = 0; r < 4; r++) O[j][r] = 0.f;
    float ls[4] = {0.f, 0.f, 0.f, 0.f};
    float m0 = -1e30f, m1 = -1e30f;
    const uint32_t ONE2 = 0x3C003C00u;

    const int nkt = qt + 1;
    for (int kt = 0; kt < nkt; kt++) {
        if (kt + 1 < nkt) {
            int st = (kt + 1) & 1;
            #pragma unroll
            for (int rep = 0; rep < 8; rep++) {
                int lin = rep * 256 + tid;
                int row = lin >> 4, sec = lin & 15;
                int s = (kt + 1) * 128 + row;
                cp16(sb + (uint32_t)(KOFF(st) + row * AKSTR + sec * 16),
                     g_k16 + (((size_t)(b * SS + s)) * NKV + kvh) * DD + sec * 8);
                cp16(sb + (uint32_t)(VOFF(st) + row * AKSTR + sec * 16),
                     g_v16 + (((size_t)(b * SS + s)) * NKV + kvh) * DD + sec * 8);
            }
            CP_COMMIT();
            CP_WAIT(1);
        } else {
            CP_WAIT(0);
        }
        __syncthreads();

        if (kt == 0) {
            #pragma unroll
            for (int kk = 0; kk < 8; kk++)
                ldsm4(qf[kk], sb + (uint32_t)((w * 16 + lq) * AKSTR + (kk * 16 + 8 * lh) * 2));
        }
        int cur = kt & 1;

        float s[16][4];
        #pragma unroll
        for (int j = 0; j < 16; j++)
            #pragma unroll
            for (int r = 0; r < 4; r++) s[j][r] = 0.f;
        #pragma unroll
        for (int kk = 0; kk < 8; kk++) {
            #pragma unroll
            for (int j2 = 0; j2 < 8; j2++) {
                uint32_t r[4];
                ldsm4(r, sb + (uint32_t)(KOFF(cur) + (j2 * 16 + lq) * AKSTR
                                         + (kk * 16 + 8 * lh) * 2));
                uint32_t b0[2] = { r[0], r[2] }, b1[2] = { r[1], r[3] };
                mma16816(s[2 * j2], qf[kk], b0);
                mma16816(s[2 * j2 + 1], qf[kk], b1);
            }
        }
        if (kt == qt) {
            int row0 = qt * 128 + w * 16 + g;
            #pragma unroll
            for (int j = 0; j < 16; j++) {
                int col = kt * 128 + j * 8 + 2 * c;
                if (col > row0)         s[j][0] = -1e30f;
                if (col + 1 > row0)     s[j][1] = -1e30f;
                if (col > row0 + 8)     s[j][2] = -1e30f;
                if (col + 1 > row0 + 8) s[j][3] = -1e30f;
            }
        }
        float r0 = -1e30f, r1 = -1e30f;
        #pragma unroll
        for (int j = 0; j < 16; j++) {
            r0 = fmaxf(r0, fmaxf(s[j][0], s[j][1]));
            r1 = fmaxf(r1, fmaxf(s[j][2], s[j][3]));
        }
        r0 = fmaxf(r0, __shfl_xor_sync(0xffffffffu, r0, 1));
        r0 = fmaxf(r0, __shfl_xor_sync(0xffffffffu, r0, 2));
        r1 = fmaxf(r1, __shfl_xor_sync(0xffffffffu, r1, 1));
        r1 = fmaxf(r1, __shfl_xor_sync(0xffffffffu, r1, 2));
        float mn0 = fmaxf(m0, r0), mn1 = fmaxf(m1, r1);
        float a0 = __expf(m0 - mn0), a1 = __expf(m1 - mn1);
        m0 = mn0; m1 = mn1;
        float nl0 = mn0 * L2E, nl1 = mn1 * L2E;

        uint32_t ph[16][2];
        #pragma unroll
        for (int j = 0; j < 16; j++) {
            ph[j][0] = expx2_h2(fmaf(s[j][0], L2E, -nl0), fmaf(s[j][1], L2E, -nl0));
            ph[j][1] = expx2_h2(fmaf(s[j][2], L2E, -nl1), fmaf(s[j][3], L2E, -nl1));
        }
        #pragma unroll
        for (int j = 0; j < 16; j++) {
            O[j][0] *= a0; O[j][1] *= a0;
            O[j][2] *= a1; O[j][3] *= a1;
        }
        ls[0] *= a0; ls[1] *= a0; ls[2] *= a1; ls[3] *= a1;

        uint32_t bone[2] = { ONE2, ONE2 };
        #pragma unroll
        for (int kk2 = 0; kk2 < 8; kk2++) {
            uint32_t pa[4] = { ph[2 * kk2][0], ph[2 * kk2][1],
                               ph[2 * kk2 + 1][0], ph[2 * kk2 + 1][1] };
            mma16816(ls, pa, bone);
            #pragma unroll
            for (int j2 = 0; j2 < 8; j2++) {
                uint32_t r[4];
                ldsm4t(r, sb + (uint32_t)(VOFF(cur) + (kk2 * 16 + lq) * AKSTR
                                          + (j2 * 16 + 8 * lh) * 2));
                mma16816(O[2 * j2], pa, r);
                mma16816(O[2 * j2 + 1], pa, r + 2);
            }
        }
        __syncthreads();
    }

    float inv0 = 1.f / ls[0], inv1 = 1.f / ls[2];
    int row0 = qt * 128 + w * 16 + g;
    __half* op0 = g_ctx16 + (((size_t)(b * SS + row0)) * NH + h) * DD;
    __half* op1 = g_ctx16 + (((size_t)(b * SS + row0 + 8)) * NH + h) * DD;
    #pragma unroll
    for (int j = 0; j < 16; j++) {
        int col = j * 8 + 2 * c;
        *(__half2*)(op0 + col) = __floats2half2_rn(O[j][0] * inv0, O[j][1] * inv0);
        *(__half2*)(op1 + col) = __floats2half2_rn(O[j][2] * inv1, O[j][3] * inv1);
    }
}

// ---------------- launch ----------------
extern "C" void kernel_launch(void* const* d_in, const int* in_sizes, int n_in,
                              void* d_out, int out_size)
{
    const float* hidden = (const float*)d_in[0];
    const float* lnw    = (const float*)d_in[1];
    const float* Wq     = (const float*)d_in[2];
    const float* bq     = (const float*)d_in[3];
    const float* Wk     = (const float*)d_in[4];
    const float* bk     = (const float*)d_in[5];
    const float* Wv     = (const float*)d_in[6];
    const float* bv     = (const float*)d_in[7];
    const float* Wo     = (const float*)d_in[8];
    const float* cosb   = (const float*)d_in[9];
    const float* sinb   = (const float*)d_in[10];
    const float* kc_in  = (const float*)d_in[11];
    const float* vc_in  = (const float*)d_in[12];
    const int*   pos    = (const int*)d_in[13];

    float* out    = (float*)d_out;
    float* kc_out = out + (size_t)BB * SS * HIDN;
    float* vc_out = kc_out + (size_t)BB * MAXS * NKV * DD;

    __half *ph, *pctx, *pw, *pwo;
    cudaGetSymbolAddress((void**)&ph,   g_h16);
    cudaGetSymbolAddress((void**)&pctx, g_ctx16);
    cudaGetSymbolAddress((void**)&pw,   g_w16);
    cudaGetSymbolAddress((void**)&pwo,  g_wo16);

    // 1. fused prep: rmsnorm + weight transposes + cache base copy (one launch)
    prep_kernel<<<PREP_COPY, 256>>>(hidden, lnw, Wq, Wk, Wv, Wo,
                                    kc_in, vc_in, kc_out, vc_out);

    // 2. fused QKV GEMM + bias + RoPE + qscale + cache writes
    cudaFuncSetAttribute(h16_gemm_kernel<0>, cudaFuncAttributeMaxDynamicSharedMemorySize, GSMEM);
    h16_gemm_kernel<0><<<dim3(24, 32), 256, GSMEM>>>(
        ph, pw, bq, bk, bv, nullptr, cosb, sinb, pos, kc_out, vc_out, nullptr);

    // 3. attention
    cudaFuncSetAttribute(attn16_kernel, cudaFuncAttributeMaxDynamicSharedMemorySize, ASMEM);
    attn16_kernel<<<512, 256, ASMEM>>>();

    // 4. Wo GEMM + residual
    cudaFuncSetAttribute(h16_gemm_kernel<1>, cudaFuncAttributeMaxDynamicSharedMemorySize, GSMEM);
    h16_gemm_kernel<1><<<dim3(16, 32), 256, GSMEM>>>(
        pctx, pwo, nullptr, nullptr, nullptr, hidden, nullptr, nullptr, nullptr,
        nullptr, nullptr, out);
}